// round 11
// baseline (speedup 1.0000x reference)
#include <cuda_runtime.h>
#include <cuda_bf16.h>
#include <cstdint>

// StimulusLayer: dist[b,o] = max_i |x[b,i] - stim[o,i]| (Chebyshev),
// out = state*0.95 + sigmoid((a-dist)*b).  B=128, I=256, O=4096.
//
// R10: register-resident stim. lane = (o-pair, k-slice): thread owns
// stim[2][32] in 64 regs (loaded once). Loop 32 b: x via dedup'd LDG.128
// (8 distinct 16B/warp, L1-hot), 128 FP, 1 STS. smem only for k-slice
// partials; one barrier; coalesced epilogue. 512 blocks x 128 thr.

#define B_DIM 128
#define I_DIM 256
#define O_DIM 4096
#define BSTRIDE 136              // float2 per b-row in red[] (8 ks * 17)

__global__ __launch_bounds__(128, 4)
void stimulus_kernel(const float* __restrict__ x,
                     const float* __restrict__ stim,
                     const float* __restrict__ a,
                     const float* __restrict__ bvec,
                     const float* __restrict__ state,
                     float* __restrict__ out)
{
    __shared__ float2 red[32 * BSTRIDE];   // ~34 KB

    const int tid  = threadIdx.x;          // 0..127
    const int w    = tid >> 5;             // warp 0..3
    const int lane = tid & 31;
    const int op   = lane >> 3;            // o-pair within warp 0..3
    const int ks   = lane & 7;             // k-slice 0..7 (32 k each)
    const int p    = w * 4 + op;           // o-pair within block 0..15

    const int bx = blockIdx.x;             // o block (32 o)
    const int b0 = blockIdx.y * 32;        // b block (32 b)
    const int my_o = bx * 32 + p * 2;

    const float4* __restrict__ s4 = (const float4*)stim;
    const float4* __restrict__ x4 = (const float4*)x;

    // ---- stim -> registers (once): s[jo][j] = stim[my_o+jo][ks*32 + 4j..] ----
    float4 s[2][8];
    #pragma unroll
    for (int jo = 0; jo < 2; jo++)
        #pragma unroll
        for (int j = 0; j < 8; j++)
            s[jo][j] = s4[(my_o + jo) * (I_DIM / 4) + ks * 8 + j];

    // ---- main loop over 32 b ----
    const float4* xrow = x4 + b0 * (I_DIM / 4) + ks * 8;
    #pragma unroll 2
    for (int b = 0; b < 32; b++) {
        float4 xv[8];
        #pragma unroll
        for (int j = 0; j < 8; j++)
            xv[j] = xrow[j];               // warp: 8 distinct 16B, 4-way dedup
        xrow += I_DIM / 4;

        float m0a = 0.f, m0b = 0.f, m1a = 0.f, m1b = 0.f;
        #pragma unroll
        for (int j = 0; j < 8; j++) {
            m0a = fmaxf(m0a, fabsf(xv[j].x - s[0][j].x));
            m0b = fmaxf(m0b, fabsf(xv[j].y - s[0][j].y));
            m0a = fmaxf(m0a, fabsf(xv[j].z - s[0][j].z));
            m0b = fmaxf(m0b, fabsf(xv[j].w - s[0][j].w));
            m1a = fmaxf(m1a, fabsf(xv[j].x - s[1][j].x));
            m1b = fmaxf(m1b, fabsf(xv[j].y - s[1][j].y));
            m1a = fmaxf(m1a, fabsf(xv[j].z - s[1][j].z));
            m1b = fmaxf(m1b, fabsf(xv[j].w - s[1][j].w));
        }
        // partial over this thread's 32 k, for o-pair (my_o, my_o+1)
        red[b * BSTRIDE + ks * 17 + p] =
            make_float2(fmaxf(m0a, m0b), fmaxf(m1a, m1b));
    }
    __syncthreads();

    // ---- epilogue: warp w handles b rows w*8..w*8+7; lane <-> o ----
    const float* redf = (const float*)red;
    const int o  = bx * 32 + lane;         // dist float index within row = lane
    const float av = a[o];
    const float bv = bvec[o];

    #pragma unroll
    for (int r = 0; r < 8; r++) {
        const int bb = w * 8 + r;
        float d = 0.f;
        #pragma unroll
        for (int k = 0; k < 8; k++)        // conflict-free: bank = (34k+lane)%32
            d = fmaxf(d, redf[bb * (2 * BSTRIDE) + k * 34 + lane]);
        const float z   = (av - d) * bv;
        const float val = 1.0f / (1.0f + __expf(-z));
        const long  g   = (long)(b0 + bb) * O_DIM + o;
        out[g] = state[g] * 0.95f + val;   // coalesced 128B per row
    }
}

extern "C" void kernel_launch(void* const* d_in, const int* in_sizes, int n_in,
                              void* d_out, int out_size)
{
    const float* x     = (const float*)d_in[0];   // (128, 256)
    const float* stim  = (const float*)d_in[1];   // (4096, 256)
    const float* a     = (const float*)d_in[2];   // (4096,)
    const float* bvec  = (const float*)d_in[3];   // (4096,)
    const float* state = (const float*)d_in[4];   // (128, 4096)
    float* out = (float*)d_out;                   // (128, 4096)

    dim3 grid(O_DIM / 32, B_DIM / 32);            // 128 x 4 = 512 blocks
    stimulus_kernel<<<grid, 128>>>(x, stim, a, bvec, state, out);
}

// round 13
// speedup vs baseline: 3.7722x; 3.7722x over previous
#include <cuda_runtime.h>
#include <cuda_bf16.h>
#include <cstdint>

// StimulusLayer: dist[b,o] = max_i |x[b,i] - stim[o,i]| (Chebyshev),
// out = state*0.95 + sigmoid((a-dist)*b).  B=128, I=256, O=4096.
//
// R12 = R11 with the ow-offset bug fixed in the stim smem read.
// Block 256thr/8warps = (kg 0..3 k-split) x (ow 0..1), warp tile 16b x 32o x 64k,
// thread tile 4b x 4o. Stage x(16KB)+stim(68KB) once, ONE barrier, then pure
// register compute (2 smem wavefronts per 128 FP). Partials reduced via smem.

#define B_DIM 128
#define I_DIM 256
#define O_DIM 4096

#define XPITCH4  65          // x row pitch in float4 (64 + 1 pad)
#define SPITCH4  17          // stim row pitch in float4 (16 + 1 pad)
#define RPITCH   72          // red row pitch in floats (64 + 8 pad)

#define XS_F4    (16 * XPITCH4)            // 1040 f4
#define SS_F4    (64 * SPITCH4)            // per k-group: 1088 f4
#define SMEM_X   0
#define SMEM_S   (XS_F4 * 16)              // bytes
#define SMEM_R   (SMEM_S + 4 * SS_F4 * 16)
#define SMEM_TOT (SMEM_R + 4 * 16 * RPITCH * 4)   // ~104.7 KB

__device__ __forceinline__ void cp_async16(uint32_t saddr, const void* gptr) {
    asm volatile("cp.async.cg.shared.global [%0], [%1], 16;" :: "r"(saddr), "l"(gptr));
}

__global__ __launch_bounds__(256, 2)
void stimulus_kernel(const float* __restrict__ x,
                     const float* __restrict__ stim,
                     const float* __restrict__ a,
                     const float* __restrict__ bvec,
                     const float* __restrict__ state,
                     float* __restrict__ out)
{
    extern __shared__ char smem[];
    float* xs  = (float*)(smem + SMEM_X);            // [16][260] floats
    float* ss  = (float*)(smem + SMEM_S);            // [4][64*68] floats
    float* red = (float*)(smem + SMEM_R);            // [4][16*72] floats

    const int tid  = threadIdx.x;        // 0..255
    const int w    = tid >> 5;           // warp 0..7
    const int lane = tid & 31;
    const int kg   = w >> 1;             // k-group 0..3 (64 k each)
    const int ow   = w & 1;              // o-half 0..1
    const int lb   = lane >> 3;          // 0..3
    const int lo   = lane & 7;           // 0..7

    const int b0 = blockIdx.y * 16;
    const int o0 = blockIdx.x * 64;

    const float4* __restrict__ x4 = (const float4*)x;    // row = 64 f4
    const float4* __restrict__ s4 = (const float4*)stim; // row = 64 f4

    const uint32_t xs_b = (uint32_t)__cvta_generic_to_shared(xs);
    const uint32_t ss_b = (uint32_t)__cvta_generic_to_shared(ss);

    // ---- stage x: 16 rows x 64 f4, 4 per thread (contiguous per warp) ----
    #pragma unroll
    for (int i = 0; i < 4; i++) {
        int idx = tid + 256 * i;                   // 0..1023
        int row = idx >> 6, col = idx & 63;
        cp_async16(xs_b + (row * XPITCH4 + col) * 16,
                   &x4[(b0 + row) * 64 + col]);
    }
    // ---- stage stim: group kg = 64 rows x 16 f4; 2 warps per group ----
    #pragma unroll
    for (int i = 0; i < 16; i++) {
        int idx = lane + 32 * i;                   // 0..511
        int row = ow * 32 + (idx >> 4);            // 0..63
        int col = idx & 15;                        // f4 col in group's 64k
        cp_async16(ss_b + (kg * SS_F4 + row * SPITCH4 + col) * 16,
                   &s4[(o0 + row) * 64 + kg * 16 + col]);
    }
    asm volatile("cp.async.wait_all;" ::: "memory");
    __syncthreads();                               // the only pre-reduce barrier

    // ---- pure register mainloop: this warp's 64 k, o-strip ow*32.. ----
    const float* xb = xs + kg * 64;                // k offset within x row
    const float* sb = ss + kg * (SS_F4 * 4)        // group's stim (floats)
                         + (ow * 32) * (SPITCH4 * 4);   // <-- R12 FIX

    float acc[4][4];
    #pragma unroll
    for (int jb = 0; jb < 4; jb++)
        #pragma unroll
        for (int jo = 0; jo < 4; jo++) acc[jb][jo] = 0.0f;

    #pragma unroll
    for (int k4 = 0; k4 < 16; k4++) {
        float4 xv[4], sv[4];
        #pragma unroll
        for (int jb = 0; jb < 4; jb++)             // 4 x 16B dedup -> 1 wf
            xv[jb] = *(const float4*)&xb[(lb + 4 * jb) * (XPITCH4 * 4) + k4 * 4];
        #pragma unroll
        for (int jo = 0; jo < 4; jo++)             // banks {0,4,..,28} -> 1 wf
            sv[jo] = *(const float4*)&sb[(lo + 8 * jo) * (SPITCH4 * 4) + k4 * 4];

        #pragma unroll
        for (int jb = 0; jb < 4; jb++) {
            #pragma unroll
            for (int jo = 0; jo < 4; jo++) {
                float mm = acc[jb][jo];
                mm = fmaxf(mm, fabsf(xv[jb].x - sv[jo].x));
                mm = fmaxf(mm, fabsf(xv[jb].y - sv[jo].y));
                mm = fmaxf(mm, fabsf(xv[jb].z - sv[jo].z));
                mm = fmaxf(mm, fabsf(xv[jb].w - sv[jo].w));
                acc[jb][jo] = mm;
            }
        }
    }

    // ---- write k-group partials (pitch 72: conflict-free) ----
    #pragma unroll
    for (int jb = 0; jb < 4; jb++) {
        const int b = lb + 4 * jb;
        #pragma unroll
        for (int jo = 0; jo < 4; jo++) {
            const int o = ow * 32 + lo + 8 * jo;
            red[kg * (16 * RPITCH) + b * RPITCH + o] = acc[jb][jo];
        }
    }
    __syncthreads();

    // ---- reduce 4 k-groups + sigmoid + state (4 outputs/thread) ----
    #pragma unroll
    for (int i = 0; i < 4; i++) {
        const int idx = tid + 256 * i;             // 0..1023
        const int b   = idx >> 6;                  // 0..15
        const int o   = idx & 63;                  // lanes -> consecutive o
        float d = red[0 * (16 * RPITCH) + b * RPITCH + o];
        d = fmaxf(d, red[1 * (16 * RPITCH) + b * RPITCH + o]);
        d = fmaxf(d, red[2 * (16 * RPITCH) + b * RPITCH + o]);
        d = fmaxf(d, red[3 * (16 * RPITCH) + b * RPITCH + o]);
        const int og = o0 + o;
        const float z   = (a[og] - d) * bvec[og];
        const float val = 1.0f / (1.0f + __expf(-z));
        const long  g   = (long)(b0 + b) * O_DIM + og;
        out[g] = state[g] * 0.95f + val;           // coalesced 128B
    }
}

extern "C" void kernel_launch(void* const* d_in, const int* in_sizes, int n_in,
                              void* d_out, int out_size)
{
    const float* x     = (const float*)d_in[0];   // (128, 256)
    const float* stim  = (const float*)d_in[1];   // (4096, 256)
    const float* a     = (const float*)d_in[2];   // (4096,)
    const float* bvec  = (const float*)d_in[3];   // (4096,)
    const float* state = (const float*)d_in[4];   // (128, 4096)
    float* out = (float*)d_out;                   // (128, 4096)

    static int smem_set = 0;                      // idempotent attribute set
    if (!smem_set) {
        cudaFuncSetAttribute(stimulus_kernel,
                             cudaFuncAttributeMaxDynamicSharedMemorySize, SMEM_TOT);
        smem_set = 1;
    }

    dim3 grid(O_DIM / 64, B_DIM / 16);            // 64 x 8 = 512 blocks
    stimulus_kernel<<<grid, 256, SMEM_TOT>>>(x, stim, a, bvec, state, out);
}